// round 5
// baseline (speedup 1.0000x reference)
#include <cuda_runtime.h>
#include <cuda_bf16.h>
#include <mma.h>
#include <cstdint>

using namespace nvcuda;

// ---------------- problem constants ----------------
#define BATCH 4
#define SEQ 8192
#define DM 1024
#define NH 16
#define HD 64
#define NCHUNK 32
#define MTOT (BATCH * SEQ) // 32768

// ---------------- scratch (device globals; no allocs) ----------------
__device__ float g_q[MTOT * DM];
__device__ float g_k[MTOT * DM];
__device__ float g_v[MTOT * DM];
__device__ __nv_bfloat16 g_ah[MTOT * DM]; // hi split of x, later of attn-out
__device__ __nv_bfloat16 g_al[MTOT * DM]; // lo split
__device__ __nv_bfloat16 g_wh[4 * DM * DM]; // transposed weights hi (q,k,v,o)
__device__ __nv_bfloat16 g_wl[4 * DM * DM]; // transposed weights lo

__device__ __forceinline__ uint32_t smem_to_u32(const void* smem_ptr) {
    uint32_t addr;
    asm("{ .reg .u64 tmp; cvta.to.shared.u64 tmp, %1; cvt.u32.u64 %0, tmp; }"
        : "=r"(addr) : "l"(smem_ptr));
    return addr;
}

__device__ __forceinline__ void cp16(uint32_t dst, const void* src) {
    asm volatile("cp.async.cg.shared.global [%0], [%1], 16;"
                 :: "r"(dst), "l"(src) : "memory");
}
__device__ __forceinline__ void cp_commit() {
    asm volatile("cp.async.commit_group;" ::: "memory");
}
template <int N>
__device__ __forceinline__ void cp_wait() {
    asm volatile("cp.async.wait_group %0;" :: "n"(N) : "memory");
}

__device__ __forceinline__ void split1(float x, __nv_bfloat16& h, __nv_bfloat16& l) {
    h = __float2bfloat16_rn(x);
    l = __float2bfloat16_rn(x - __bfloat162float(h));
}

// ===========================================================================
// prep: split fp32 -> bf16 hi/lo
// ===========================================================================
__global__ __launch_bounds__(256) void splitx_kernel(
    const float4* __restrict__ in, __nv_bfloat162* __restrict__ h,
    __nv_bfloat162* __restrict__ l)
{
    size_t i = (size_t)blockIdx.x * 256 + threadIdx.x;
    float4 v = in[i];
    __nv_bfloat16 h0, h1, h2, h3, l0, l1, l2, l3;
    split1(v.x, h0, l0); split1(v.y, h1, l1);
    split1(v.z, h2, l2); split1(v.w, h3, l3);
    __nv_bfloat162 a; a.x = h0; a.y = h1;
    __nv_bfloat162 b; b.x = h2; b.y = h3;
    __nv_bfloat162 c; c.x = l0; c.y = l1;
    __nv_bfloat162 d; d.x = l2; d.y = l3;
    h[2 * i] = a; h[2 * i + 1] = b;
    l[2 * i] = c; l[2 * i + 1] = d;
}

// ===========================================================================
// prep: W[K,N] fp32 -> Wt[N,K] bf16 hi/lo (transpose + split)
// ===========================================================================
__global__ __launch_bounds__(256) void wtrans_kernel(
    const float* __restrict__ W, __nv_bfloat16* __restrict__ th,
    __nv_bfloat16* __restrict__ tl)
{
    __shared__ float tile[32][33];
    const int n0 = blockIdx.x * 32, k0 = blockIdx.y * 32;
    const int tx = threadIdx.x, ty = threadIdx.y;
    for (int r = ty; r < 32; r += 8)
        tile[r][tx] = W[(size_t)(k0 + r) * DM + n0 + tx];
    __syncthreads();
    for (int r = ty; r < 32; r += 8) {
        float v = tile[tx][r];
        __nv_bfloat16 h, l;
        split1(v, h, l);
        size_t o = (size_t)(n0 + r) * DM + k0 + tx;
        th[o] = h;
        tl[o] = l;
    }
}

// ===========================================================================
// GEMM: C[M,1024] = A[M,1024] @ Bt[1024,1024]^T, bf16x3 (pre-split hi/lo),
// fp32 WMMA accumulation. Tile 128x256, BK=64, 2-stage cp.async pipeline,
// 256 threads (8 warps, warp tile 64x64).
// smem per stage: Ah 128x72, Al 128x72, Bh 256x72, Bl 256x72 (bf16) = 108KB.
// ===========================================================================
#define BKC 64
#define NCH2 (DM / BKC) // 16
#define SSTRIDE 72                      // elements (144B, 16B aligned)
#define AH_OFF 0
#define AL_OFF (128 * SSTRIDE * 2)      // 18432 B
#define BH_OFF (2 * 128 * SSTRIDE * 2)  // 36864 B
#define BL_OFF (BH_OFF + 256 * SSTRIDE * 2) // 73728 B
#define STG_B (BL_OFF + 256 * SSTRIDE * 2)  // 110592 B per stage
#define GEMM_SMEM (2 * STG_B)           // 221184 B

__global__ __launch_bounds__(256, 1) void gemm_tc(
    const __nv_bfloat16* __restrict__ Ahg, const __nv_bfloat16* __restrict__ Alg,
    const __nv_bfloat16* __restrict__ Bhg, const __nv_bfloat16* __restrict__ Blg,
    float* __restrict__ C)
{
    extern __shared__ char smem[];
    const uint32_t smem_u32 = smem_to_u32(smem);
    const int tid = threadIdx.x;
    const int wid = tid >> 5;
    const int wm = wid >> 2; // 0..1 -> 64-row block
    const int wn = wid & 3;  // 0..3 -> 64-col block
    const int bm = blockIdx.y * 128, bn = blockIdx.x * 256;

    const __nv_bfloat16* pAh = Ahg + (size_t)bm * DM;
    const __nv_bfloat16* pAl = Alg + (size_t)bm * DM;
    const __nv_bfloat16* pBh = Bhg + (size_t)bn * DM;
    const __nv_bfloat16* pBl = Blg + (size_t)bn * DM;

    // ---- async chunk loader: 6144 16B units, 24 per thread ----
    auto load_chunk = [&](int c, int stage) {
        const int kc = c * BKC;
        const uint32_t sbase = smem_u32 + stage * STG_B;
#pragma unroll
        for (int i = 0; i < 24; i++) {
            const int idx = i * 256 + tid;
            if (i < 4) { // Ah: idx 0..1023
                const int row = idx >> 3, u = idx & 7;
                cp16(sbase + AH_OFF + row * (SSTRIDE * 2) + u * 16,
                     pAh + (size_t)row * DM + kc + u * 8);
            } else if (i < 8) { // Al: idx 1024..2047
                const int r2 = idx - 1024;
                const int row = r2 >> 3, u = r2 & 7;
                cp16(sbase + AL_OFF + row * (SSTRIDE * 2) + u * 16,
                     pAl + (size_t)row * DM + kc + u * 8);
            } else if (i < 16) { // Bh: idx 2048..4095
                const int r2 = idx - 2048;
                const int row = r2 >> 3, u = r2 & 7;
                cp16(sbase + BH_OFF + row * (SSTRIDE * 2) + u * 16,
                     pBh + (size_t)row * DM + kc + u * 8);
            } else { // Bl: idx 4096..6143
                const int r2 = idx - 4096;
                const int row = r2 >> 3, u = r2 & 7;
                cp16(sbase + BL_OFF + row * (SSTRIDE * 2) + u * 16,
                     pBl + (size_t)row * DM + kc + u * 8);
            }
        }
    };

    wmma::fragment<wmma::accumulator, 16, 16, 16, float> acc[4][4];
#pragma unroll
    for (int i = 0; i < 4; i++)
#pragma unroll
        for (int j = 0; j < 4; j++)
            wmma::fill_fragment(acc[i][j], 0.0f);

    // prologue
    load_chunk(0, 0);
    cp_commit();

#pragma unroll 1
    for (int c = 0; c < NCH2; c++) {
        const int stage = c & 1;
        if (c + 1 < NCH2) {
            load_chunk(c + 1, (c + 1) & 1);
            cp_commit();
            cp_wait<1>();
        } else {
            cp_wait<0>();
        }
        __syncthreads();

        const __nv_bfloat16* sAh = reinterpret_cast<const __nv_bfloat16*>(smem + stage * STG_B + AH_OFF);
        const __nv_bfloat16* sAl = reinterpret_cast<const __nv_bfloat16*>(smem + stage * STG_B + AL_OFF);
        const __nv_bfloat16* sBh = reinterpret_cast<const __nv_bfloat16*>(smem + stage * STG_B + BH_OFF);
        const __nv_bfloat16* sBl = reinterpret_cast<const __nv_bfloat16*>(smem + stage * STG_B + BL_OFF);

#pragma unroll
        for (int ks = 0; ks < 4; ks++) {
            wmma::fragment<wmma::matrix_a, 16, 16, 16, __nv_bfloat16, wmma::row_major> ah[4];
            wmma::fragment<wmma::matrix_b, 16, 16, 16, __nv_bfloat16, wmma::col_major> bh[4];
#pragma unroll
            for (int i = 0; i < 4; i++)
                wmma::load_matrix_sync(ah[i], sAh + (wm * 64 + i * 16) * SSTRIDE + ks * 16, SSTRIDE);
#pragma unroll
            for (int j = 0; j < 4; j++)
                wmma::load_matrix_sync(bh[j], sBh + (wn * 64 + j * 16) * SSTRIDE + ks * 16, SSTRIDE);
            // hh
#pragma unroll
            for (int i = 0; i < 4; i++)
#pragma unroll
                for (int j = 0; j < 4; j++)
                    wmma::mma_sync(acc[i][j], ah[i], bh[j], acc[i][j]);
            // lh: Al x Bh
            {
                wmma::fragment<wmma::matrix_a, 16, 16, 16, __nv_bfloat16, wmma::row_major> al[4];
#pragma unroll
                for (int i = 0; i < 4; i++)
                    wmma::load_matrix_sync(al[i], sAl + (wm * 64 + i * 16) * SSTRIDE + ks * 16, SSTRIDE);
#pragma unroll
                for (int i = 0; i < 4; i++)
#pragma unroll
                    for (int j = 0; j < 4; j++)
                        wmma::mma_sync(acc[i][j], al[i], bh[j], acc[i][j]);
            }
            // hl: Ah x Bl
            {
                wmma::fragment<wmma::matrix_b, 16, 16, 16, __nv_bfloat16, wmma::col_major> bl[4];
#pragma unroll
                for (int j = 0; j < 4; j++)
                    wmma::load_matrix_sync(bl[j], sBl + (wn * 64 + j * 16) * SSTRIDE + ks * 16, SSTRIDE);
#pragma unroll
                for (int i = 0; i < 4; i++)
#pragma unroll
                    for (int j = 0; j < 4; j++)
                        wmma::mma_sync(acc[i][j], ah[i], bl[j], acc[i][j]);
            }
        }
        __syncthreads();
    }

#pragma unroll
    for (int i = 0; i < 4; i++)
#pragma unroll
        for (int j = 0; j < 4; j++)
            wmma::store_matrix_sync(
                C + (size_t)(bm + wm * 64 + i * 16) * DM + bn + wn * 64 + j * 16,
                acc[i][j], DM, wmma::mem_row_major);
}

// ===========================================================================
// Chunked local attention, 256 threads. Writes bf16 hi/lo splits directly.
// ===========================================================================
#define ATTN_SMEM_FLOATS (64 * 65 + 128 * 65 + 128 * 65 + 64 * 130)
#define ATTN_SMEM_BYTES (ATTN_SMEM_FLOATS * 4)

__global__ __launch_bounds__(256) void attn_kernel(
    const float* __restrict__ q, const float* __restrict__ k,
    const float* __restrict__ v, __nv_bfloat16* __restrict__ oh,
    __nv_bfloat16* __restrict__ ol)
{
    extern __shared__ float smemf[];
    float* Qs = smemf;            // [64][65]
    float* Ks = Qs + 64 * 65;     // [128][65]
    float* Vs = Ks + 128 * 65;    // [128][65]
    float* Ss = Vs + 128 * 65;    // [64][130]

    const int bid = blockIdx.x;
    const int rtile = bid & 3;
    const int head = (bid >> 2) & 15;
    const int chunk = (bid >> 6) & (NCHUNK - 1);
    const int b = bid >> 11;

    const int tid = threadIdx.x;
    const int c0 = rtile * 64 - 64;
    const size_t base = ((size_t)(b * SEQ + chunk * 256)) * DM + head * HD;

    for (int idx = tid; idx < 64 * 16; idx += 256) {
        int row = idx >> 4;
        int c = (idx & 15) << 2;
        float4 val = *reinterpret_cast<const float4*>(
            q + base + (size_t)(rtile * 64 + row) * DM + c);
        float* dst = Qs + row * 65 + c;
        dst[0] = val.x; dst[1] = val.y; dst[2] = val.z; dst[3] = val.w;
    }
    for (int idx = tid; idx < 128 * 16; idx += 256) {
        int row = idx >> 4;
        int c = (idx & 15) << 2;
        int jc = c0 + row;
        float4 kv = make_float4(0.f, 0.f, 0.f, 0.f);
        float4 vv = make_float4(0.f, 0.f, 0.f, 0.f);
        if (jc >= 0) {
            kv = *reinterpret_cast<const float4*>(k + base + (size_t)jc * DM + c);
            vv = *reinterpret_cast<const float4*>(v + base + (size_t)jc * DM + c);
        }
        float* dk = Ks + row * 65 + c;
        dk[0] = kv.x; dk[1] = kv.y; dk[2] = kv.z; dk[3] = kv.w;
        float* dv = Vs + row * 65 + c;
        dv[0] = vv.x; dv[1] = vv.y; dv[2] = vv.z; dv[3] = vv.w;
    }
    __syncthreads();

    // ---- scores: S[64][128], 256 threads: rows {rg+16r}, cols {cg+16j} ----
    {
        const int rg = tid >> 4;  // 0..15
        const int cg = tid & 15;  // 0..15
        float acc[4][8];
#pragma unroll
        for (int r = 0; r < 4; r++)
#pragma unroll
            for (int jj = 0; jj < 8; jj++) acc[r][jj] = 0.f;

        for (int d = 0; d < 64; d++) {
            float qv0 = Qs[rg * 65 + d];
            float qv1 = Qs[(rg + 16) * 65 + d];
            float qv2 = Qs[(rg + 32) * 65 + d];
            float qv3 = Qs[(rg + 48) * 65 + d];
#pragma unroll
            for (int jj = 0; jj < 8; jj++) {
                float kv = Ks[(cg + 16 * jj) * 65 + d];
                acc[0][jj] += qv0 * kv;
                acc[1][jj] += qv1 * kv;
                acc[2][jj] += qv2 * kv;
                acc[3][jj] += qv3 * kv;
            }
        }
        const float scale = 0.125f;
#pragma unroll
        for (int r = 0; r < 4; r++)
#pragma unroll
            for (int jj = 0; jj < 8; jj++)
                Ss[(rg + 16 * r) * 130 + cg + 16 * jj] = acc[r][jj] * scale;
    }
    __syncthreads();

    // ---- masked softmax: 4 threads per row, 32 cols each ----
    {
        const int i = tid >> 2;
        const int sub = tid & 3;
        const int lo = (rtile == 0) ? 64 : i;
        const int hi = i + 64;
        float* row = Ss + i * 130 + sub * 32;
        const int jbase = sub * 32;

        float m = -1e30f;
#pragma unroll
        for (int jj = 0; jj < 32; jj++) {
            int j = jbase + jj;
            if (j >= lo && j <= hi) m = fmaxf(m, row[jj]);
        }
        m = fmaxf(m, __shfl_xor_sync(0xffffffffu, m, 1));
        m = fmaxf(m, __shfl_xor_sync(0xffffffffu, m, 2));

        float s = 0.f;
#pragma unroll
        for (int jj = 0; jj < 32; jj++) {
            int j = jbase + jj;
            float e = 0.f;
            if (j >= lo && j <= hi) {
                e = __expf(row[jj] - m);
                s += e;
            }
            row[jj] = e;
        }
        s += __shfl_xor_sync(0xffffffffu, s, 1);
        s += __shfl_xor_sync(0xffffffffu, s, 2);
        float inv = 1.0f / s;
#pragma unroll
        for (int jj = 0; jj < 32; jj++) row[jj] *= inv;
    }
    __syncthreads();

    // ---- out = P @ V : row = tid>>2, d-block = (tid&3)*16 ----
    {
        const int row = tid >> 2;
        const int cg = tid & 3;
        float acc[16];
#pragma unroll
        for (int dd = 0; dd < 16; dd++) acc[dd] = 0.f;

        for (int j = 0; j < 128; j++) {
            float p = Ss[row * 130 + j];
#pragma unroll
            for (int dd = 0; dd < 16; dd++)
                acc[dd] += p * Vs[j * 65 + cg * 16 + dd];
        }
        size_t off = base + (size_t)(rtile * 64 + row) * DM + cg * 16;
#pragma unroll
        for (int d2 = 0; d2 < 8; d2++) {
            __nv_bfloat16 h0, h1, l0, l1;
            split1(acc[d2 * 2 + 0], h0, l0);
            split1(acc[d2 * 2 + 1], h1, l1);
            __nv_bfloat162 hp; hp.x = h0; hp.y = h1;
            __nv_bfloat162 lp; lp.x = l0; lp.y = l1;
            *reinterpret_cast<__nv_bfloat162*>(oh + off + d2 * 2) = hp;
            *reinterpret_cast<__nv_bfloat162*>(ol + off + d2 * 2) = lp;
        }
    }
}

// ===========================================================================
// kernel_launch
// ===========================================================================
extern "C" void kernel_launch(void* const* d_in, const int* in_sizes, int n_in,
                              void* d_out, int out_size)
{
    (void)in_sizes; (void)n_in; (void)out_size;
    const float* x  = (const float*)d_in[0];
    const float* Wq = (const float*)d_in[1];
    const float* Wk = (const float*)d_in[2];
    const float* Wv = (const float*)d_in[3];
    const float* Wo = (const float*)d_in[4];
    float* out = (float*)d_out;

    float *q, *k, *v;
    __nv_bfloat16 *ah, *al, *wh, *wl;
    cudaGetSymbolAddress((void**)&q, g_q);
    cudaGetSymbolAddress((void**)&k, g_k);
    cudaGetSymbolAddress((void**)&v, g_v);
    cudaGetSymbolAddress((void**)&ah, g_ah);
    cudaGetSymbolAddress((void**)&al, g_al);
    cudaGetSymbolAddress((void**)&wh, g_wh);
    cudaGetSymbolAddress((void**)&wl, g_wl);

    cudaFuncSetAttribute(gemm_tc, cudaFuncAttributeMaxDynamicSharedMemorySize,
                         GEMM_SMEM);
    cudaFuncSetAttribute(attn_kernel, cudaFuncAttributeMaxDynamicSharedMemorySize,
                         ATTN_SMEM_BYTES);

    // 1) split x into bf16 hi/lo
    splitx_kernel<<<(MTOT * DM / 4) / 256, 256>>>(
        (const float4*)x, (__nv_bfloat162*)ah, (__nv_bfloat162*)al);

    // 2) transpose+split all four weights
    dim3 wgrid(DM / 32, DM / 32);
    dim3 wblk(32, 8);
    wtrans_kernel<<<wgrid, wblk>>>(Wq, wh + 0 * DM * DM, wl + 0 * DM * DM);
    wtrans_kernel<<<wgrid, wblk>>>(Wk, wh + 1 * DM * DM, wl + 1 * DM * DM);
    wtrans_kernel<<<wgrid, wblk>>>(Wv, wh + 2 * DM * DM, wl + 2 * DM * DM);
    wtrans_kernel<<<wgrid, wblk>>>(Wo, wh + 3 * DM * DM, wl + 3 * DM * DM);

    // 3) Q/K/V projections
    dim3 ggrid(DM / 256, MTOT / 128); // (4, 256)
    gemm_tc<<<ggrid, 256, GEMM_SMEM>>>(ah, al, wh + 0 * DM * DM, wl + 0 * DM * DM, q);
    gemm_tc<<<ggrid, 256, GEMM_SMEM>>>(ah, al, wh + 1 * DM * DM, wl + 1 * DM * DM, k);
    gemm_tc<<<ggrid, 256, GEMM_SMEM>>>(ah, al, wh + 2 * DM * DM, wl + 2 * DM * DM, v);

    // 4) attention (writes bf16 hi/lo into ah/al)
    attn_kernel<<<BATCH * NCHUNK * NH * 4, 256, ATTN_SMEM_BYTES>>>(q, k, v, ah, al);

    // 5) output projection
    gemm_tc<<<ggrid, 256, GEMM_SMEM>>>(ah, al, wh + 3 * DM * DM, wl + 3 * DM * DM, out);
}